// round 1
// baseline (speedup 1.0000x reference)
#include <cuda_runtime.h>

#define D_TOT 65536
#define S_TOT 1024

// Main kernel: each block owns a 32-wide slab of d (rows), sweeps all 1024 s
// in 32x32 tiles. Reads weight/bias coalesced over s, transposes enc through
// shared memory, writes hvs coalesced over d. Also accumulates
// bundled[d] = sum_s enc[d,s]*alpha[s] and emits q[d] = sign(bundled[d]).
__global__ __launch_bounds__(256) void reghd_main(
    const float* __restrict__ x,
    const float* __restrict__ weight,
    const float* __restrict__ bias,
    const float* __restrict__ alpha,
    float* __restrict__ out)   // [0]=model_result (filled by kernel2), [1..D]=q, [1+D ...]=hvs (SIZE,D)
{
    __shared__ float sx[S_TOT];
    __shared__ float sa[S_TOT];
    __shared__ float tile[32][33];   // +1 pad: conflict-free transposed reads

    const int tx  = threadIdx.x;     // 0..31  (s within tile on load, d within tile on store)
    const int ty  = threadIdx.y;     // 0..7
    const int tid = ty * 32 + tx;
    const int d0  = blockIdx.x * 32;

    for (int i = tid; i < S_TOT; i += 256) { sx[i] = x[i]; sa[i] = alpha[i]; }
    __syncthreads();

    float acc[4] = {0.f, 0.f, 0.f, 0.f};
    float* __restrict__ hvs = out + 1 + D_TOT;

    for (int s0 = 0; s0 < S_TOT; s0 += 32) {
        const float xv = sx[s0 + tx];
        const float av = sa[s0 + tx];
        #pragma unroll
        for (int r = 0; r < 4; r++) {
            const int dl = ty + 8 * r;
            const size_t idx = (size_t)(d0 + dl) * S_TOT + (size_t)(s0 + tx);
            const float p = xv * weight[idx];
            const float e = cosf(p + bias[idx]) * sinf(p);
            tile[dl][tx] = e;
            acc[r] += e * av;
        }
        __syncthreads();
        #pragma unroll
        for (int r = 0; r < 4; r++) {
            const int sl = ty + 8 * r;
            hvs[(size_t)(s0 + sl) * D_TOT + (size_t)(d0 + tx)] = tile[tx][sl];
        }
        __syncthreads();
    }

    // Reduce bundled across the 32 lanes of each warp (warp == fixed ty).
    #pragma unroll
    for (int r = 0; r < 4; r++) {
        float v = acc[r];
        #pragma unroll
        for (int off = 16; off > 0; off >>= 1)
            v += __shfl_xor_sync(0xFFFFFFFFu, v, off);
        if (tx == 0) {
            const int d = d0 + ty + 8 * r;
            out[1 + d] = (v > 0.f) ? 1.f : -1.f;
        }
    }
}

// model_result = dot(q, M). Single block, deterministic tree reduction.
__global__ __launch_bounds__(1024) void reghd_dot(
    const float* __restrict__ M,
    float* __restrict__ out)
{
    __shared__ float red[1024];
    const float* __restrict__ q = out + 1;
    float s = 0.f;
    for (int i = threadIdx.x; i < D_TOT; i += 1024)
        s += q[i] * M[i];
    red[threadIdx.x] = s;
    __syncthreads();
    #pragma unroll
    for (int k = 512; k > 0; k >>= 1) {
        if (threadIdx.x < k) red[threadIdx.x] += red[threadIdx.x + k];
        __syncthreads();
    }
    if (threadIdx.x == 0) out[0] = red[0];
}

extern "C" void kernel_launch(void* const* d_in, const int* in_sizes, int n_in,
                              void* d_out, int out_size) {
    const float* x      = (const float*)d_in[0];
    const float* weight = (const float*)d_in[1];
    const float* bias   = (const float*)d_in[2];
    const float* alpha  = (const float*)d_in[3];
    const float* M      = (const float*)d_in[4];
    // d_in[5] = ts (unused; alpha row already selected)
    float* out = (float*)d_out;

    dim3 blk(32, 8);
    reghd_main<<<D_TOT / 32, blk>>>(x, weight, bias, alpha, out);
    reghd_dot<<<1, 1024>>>(M, out);
}

// round 2
// speedup vs baseline: 1.3830x; 1.3830x over previous
#include <cuda_runtime.h>

#define D_TOT 65536
#define S_TOT 1024
#define TS    128
#define NBLK  (D_TOT / 32)   // 2048 blocks

__device__ float g_part[NBLK];

// Each block: 32 d-rows, sweeps s in 128-wide tiles with float4 loads.
// Transposes enc through shared memory: reads coalesced over s, writes hvs
// coalesced over d. Accumulates bundled[d] and per-block dot(q,M) partials.
__global__ __launch_bounds__(256, 6) void reghd_main(
    const float* __restrict__ x,
    const float* __restrict__ weight,
    const float* __restrict__ bias,
    const float* __restrict__ alpha,
    const float* __restrict__ M,
    float* __restrict__ out)   // [0]=model_result, [1..D]=q, [1+D ...]=hvs (SIZE,D)
{
    __shared__ float4 sx[S_TOT / 4];
    __shared__ float4 sa[S_TOT / 4];
    __shared__ float  tile[32][TS + 1];   // [d][s], stride 129: conflict-free transposed reads
    __shared__ float  bpart[32];

    const int tx  = threadIdx.x;          // 0..31
    const int ty  = threadIdx.y;          // 0..7 (warp id)
    const int tid = ty * 32 + tx;
    const int d0  = blockIdx.x * 32;

    sx[tid] = ((const float4*)x)[tid];
    sa[tid] = ((const float4*)alpha)[tid];
    __syncthreads();

    float acc[4] = {0.f, 0.f, 0.f, 0.f};
    float* __restrict__ hvs = out + 1 + D_TOT;

    for (int s0 = 0; s0 < S_TOT; s0 += TS) {
        const float4 xv = sx[(s0 >> 2) + tx];
        const float4 av = sa[(s0 >> 2) + tx];

        #pragma unroll
        for (int r = 0; r < 4; r++) {
            const int    dl   = ty + 8 * r;
            const size_t base = (size_t)(d0 + dl) * S_TOT + (size_t)s0 + 4 * tx;
            const float4 w = __ldcs((const float4*)(weight + base));
            const float4 b = __ldcs((const float4*)(bias   + base));

            const float p0 = xv.x * w.x, p1 = xv.y * w.y;
            const float p2 = xv.z * w.z, p3 = xv.w * w.w;
            const float e0 = cosf(p0 + b.x) * sinf(p0);
            const float e1 = cosf(p1 + b.y) * sinf(p1);
            const float e2 = cosf(p2 + b.z) * sinf(p2);
            const float e3 = cosf(p3 + b.w) * sinf(p3);

            tile[dl][4 * tx + 0] = e0;
            tile[dl][4 * tx + 1] = e1;
            tile[dl][4 * tx + 2] = e2;
            tile[dl][4 * tx + 3] = e3;

            acc[r] += fmaf(e0, av.x, fmaf(e1, av.y, fmaf(e2, av.z, e3 * av.w)));
        }
        __syncthreads();

        // hvs writes: warp lane tx -> d, 16 s-rows per thread, coalesced 128B.
        #pragma unroll
        for (int k = 0; k < 16; k++) {
            const int sl = ty + 8 * k;
            __stcs(&hvs[(size_t)(s0 + sl) * D_TOT + (size_t)(d0 + tx)], tile[tx][sl]);
        }
        __syncthreads();
    }

    // bundled -> q -> per-block dot(q, M) partial
    #pragma unroll
    for (int r = 0; r < 4; r++) {
        float v = acc[r];
        #pragma unroll
        for (int off = 16; off > 0; off >>= 1)
            v += __shfl_xor_sync(0xFFFFFFFFu, v, off);
        if (tx == 0) {
            const int   d = d0 + ty + 8 * r;
            const float q = (v > 0.f) ? 1.f : -1.f;
            out[1 + d]     = q;
            bpart[ty + 8 * r] = q * M[d];
        }
    }
    __syncthreads();
    if (tid == 0) {
        float s = 0.f;
        #pragma unroll
        for (int i = 0; i < 32; i++) s += bpart[i];
        g_part[blockIdx.x] = s;
    }
}

// Deterministic reduction of 2048 block partials -> out[0].
__global__ __launch_bounds__(256) void reghd_reduce(float* __restrict__ out)
{
    __shared__ float red[256];
    float s = 0.f;
    for (int i = threadIdx.x; i < NBLK; i += 256)
        s += g_part[i];
    red[threadIdx.x] = s;
    __syncthreads();
    #pragma unroll
    for (int k = 128; k > 0; k >>= 1) {
        if (threadIdx.x < k) red[threadIdx.x] += red[threadIdx.x + k];
        __syncthreads();
    }
    if (threadIdx.x == 0) out[0] = red[0];
}

extern "C" void kernel_launch(void* const* d_in, const int* in_sizes, int n_in,
                              void* d_out, int out_size) {
    const float* x      = (const float*)d_in[0];
    const float* weight = (const float*)d_in[1];
    const float* bias   = (const float*)d_in[2];
    const float* alpha  = (const float*)d_in[3];
    const float* M      = (const float*)d_in[4];
    float* out = (float*)d_out;

    dim3 blk(32, 8);
    reghd_main<<<NBLK, blk>>>(x, weight, bias, alpha, M, out);
    reghd_reduce<<<1, 256>>>(out);
}

// round 3
// speedup vs baseline: 1.5534x; 1.1232x over previous
#include <cuda_runtime.h>

#define D_TOT 65536
#define S_TOT 1024
#define TS    128
#define NBLK  (D_TOT / 32)   // 2048 blocks
#define EPS   0.02f          // |bundled| below this -> precise-trig recompute

__device__ float        g_part[NBLK];
__device__ unsigned int g_ctr;   // zero at load; reset by the reducing block each call

// One fused kernel: 32 d-rows per block, s swept in 128-wide float4 tiles.
// enc computed with MUFU fast trig; smem transpose for coalesced hvs writes;
// bundled rows near the sign threshold are recomputed with precise trig.
// Last block to finish reduces the 2048 dot(q,M) partials into out[0].
__global__ __launch_bounds__(256, 6) void reghd_main(
    const float* __restrict__ x,
    const float* __restrict__ weight,
    const float* __restrict__ bias,
    const float* __restrict__ alpha,
    const float* __restrict__ M,
    float* __restrict__ out)   // [0]=model_result, [1..D]=q, [1+D ...]=hvs (SIZE,D)
{
    __shared__ float4 sx[S_TOT / 4];
    __shared__ float4 sa[S_TOT / 4];
    __shared__ float  tile[32][TS + 1];   // [d][s], pad: conflict-free transposed reads
    __shared__ float  bpart[32];
    __shared__ float  red[256];
    __shared__ bool   is_last;

    const int tx  = threadIdx.x;          // 0..31
    const int ty  = threadIdx.y;          // 0..7 (warp id)
    const int tid = ty * 32 + tx;
    const int d0  = blockIdx.x * 32;

    sx[tid] = ((const float4*)x)[tid];
    sa[tid] = ((const float4*)alpha)[tid];
    __syncthreads();

    float acc[4] = {0.f, 0.f, 0.f, 0.f};
    float* __restrict__ hvs = out + 1 + D_TOT;

    for (int s0 = 0; s0 < S_TOT; s0 += TS) {
        const float4 xv = sx[(s0 >> 2) + tx];
        const float4 av = sa[(s0 >> 2) + tx];

        #pragma unroll
        for (int r = 0; r < 4; r++) {
            const int    dl   = ty + 8 * r;
            const size_t base = (size_t)(d0 + dl) * S_TOT + (size_t)s0 + 4 * tx;
            const float4 w = __ldcs((const float4*)(weight + base));
            const float4 b = __ldcs((const float4*)(bias   + base));

            const float p0 = xv.x * w.x, p1 = xv.y * w.y;
            const float p2 = xv.z * w.z, p3 = xv.w * w.w;
            const float e0 = __cosf(p0 + b.x) * __sinf(p0);
            const float e1 = __cosf(p1 + b.y) * __sinf(p1);
            const float e2 = __cosf(p2 + b.z) * __sinf(p2);
            const float e3 = __cosf(p3 + b.w) * __sinf(p3);

            tile[dl][4 * tx + 0] = e0;
            tile[dl][4 * tx + 1] = e1;
            tile[dl][4 * tx + 2] = e2;
            tile[dl][4 * tx + 3] = e3;

            acc[r] += fmaf(e0, av.x, fmaf(e1, av.y, fmaf(e2, av.z, e3 * av.w)));
        }
        __syncthreads();

        #pragma unroll
        for (int k = 0; k < 16; k++) {
            const int sl = ty + 8 * k;
            __stcs(&hvs[(size_t)(s0 + sl) * D_TOT + (size_t)(d0 + tx)], tile[tx][sl]);
        }
        __syncthreads();
    }

    // bundled -> (guarded) q -> per-block dot(q, M) partial
    const float* xs = (const float*)sx;
    const float* as = (const float*)sa;
    #pragma unroll
    for (int r = 0; r < 4; r++) {
        float v = acc[r];
        #pragma unroll
        for (int off = 16; off > 0; off >>= 1)
            v += __shfl_xor_sync(0xFFFFFFFFu, v, off);   // all lanes hold the total

        if (fabsf(v) < EPS) {
            // Borderline sign: recompute this row with precise trig (rare, ~0.16%).
            const int d = d0 + ty + 8 * r;
            float s2 = 0.f;
            for (int s = tx; s < S_TOT; s += 32) {
                const float w = weight[(size_t)d * S_TOT + s];
                const float b = bias[(size_t)d * S_TOT + s];
                const float p = xs[s] * w;
                s2 += cosf(p + b) * sinf(p) * as[s];
            }
            #pragma unroll
            for (int off = 16; off > 0; off >>= 1)
                s2 += __shfl_xor_sync(0xFFFFFFFFu, s2, off);
            v = s2;
        }
        if (tx == 0) {
            const int   d = d0 + ty + 8 * r;
            const float q = (v > 0.f) ? 1.f : -1.f;
            out[1 + d]        = q;
            bpart[ty + 8 * r] = q * M[d];
        }
    }
    __syncthreads();
    if (tid == 0) {
        float s = 0.f;
        #pragma unroll
        for (int i = 0; i < 32; i++) s += bpart[i];
        g_part[blockIdx.x] = s;
        __threadfence();
        const unsigned int prev = atomicAdd(&g_ctr, 1u);
        is_last = (prev == NBLK - 1);
    }
    __syncthreads();

    // Last-arriving block reduces all partials (fixed order -> deterministic value).
    if (is_last) {
        float s = 0.f;
        for (int i = tid; i < NBLK; i += 256)
            s += g_part[i];
        red[tid] = s;
        __syncthreads();
        #pragma unroll
        for (int k = 128; k > 0; k >>= 1) {
            if (tid < k) red[tid] += red[tid + k];
            __syncthreads();
        }
        if (tid == 0) {
            out[0] = red[0];
            g_ctr  = 0;          // reset for next graph replay
        }
    }
}

extern "C" void kernel_launch(void* const* d_in, const int* in_sizes, int n_in,
                              void* d_out, int out_size) {
    const float* x      = (const float*)d_in[0];
    const float* weight = (const float*)d_in[1];
    const float* bias   = (const float*)d_in[2];
    const float* alpha  = (const float*)d_in[3];
    const float* M      = (const float*)d_in[4];
    float* out = (float*)d_out;

    dim3 blk(32, 8);
    reghd_main<<<NBLK, blk>>>(x, weight, bias, alpha, M, out);
}